// round 1
// baseline (speedup 1.0000x reference)
#include <cuda_runtime.h>
#include <cstdint>

#define C_   8
#define M_   2048
#define D_   2048
#define B_   256
#define CM_  (C_ * M_)
#define KNN  50
#define INVT 20.0f   // 1/TEMP, TEMP = 0.05

// ---- scratch (device globals: allocation-free rule) ----
__device__ float g_sims[(size_t)B_ * CM_];   // 16 MB
__device__ float g_partial[B_];

// ============================================================
// block reductions (all threads must call; trailing sync guards reuse)
// ============================================================
__device__ __forceinline__ float blockReduceSum(float val) {
    __shared__ float sh[32];
    int lane = threadIdx.x & 31, wid = threadIdx.x >> 5;
    #pragma unroll
    for (int o = 16; o; o >>= 1) val += __shfl_down_sync(0xffffffffu, val, o);
    if (lane == 0) sh[wid] = val;
    __syncthreads();
    int nw = (blockDim.x + 31) >> 5;
    val = (threadIdx.x < (unsigned)nw) ? sh[threadIdx.x] : 0.f;
    if (wid == 0) {
        #pragma unroll
        for (int o = 16; o; o >>= 1) val += __shfl_down_sync(0xffffffffu, val, o);
        if (lane == 0) sh[0] = val;
    }
    __syncthreads();
    val = sh[0];
    __syncthreads();
    return val;
}

__device__ __forceinline__ float blockReduceMax(float val) {
    __shared__ float sh[32];
    int lane = threadIdx.x & 31, wid = threadIdx.x >> 5;
    #pragma unroll
    for (int o = 16; o; o >>= 1) val = fmaxf(val, __shfl_down_sync(0xffffffffu, val, o));
    if (lane == 0) sh[wid] = val;
    __syncthreads();
    int nw = (blockDim.x + 31) >> 5;
    val = (threadIdx.x < (unsigned)nw) ? sh[threadIdx.x] : -3.4e38f;
    if (wid == 0) {
        #pragma unroll
        for (int o = 16; o; o >>= 1) val = fmaxf(val, __shfl_down_sync(0xffffffffu, val, o));
        if (lane == 0) sh[0] = val;
    }
    __syncthreads();
    val = sh[0];
    __syncthreads();
    return val;
}

// monotone float->uint key (total order)
__device__ __forceinline__ unsigned fkey(float f) {
    unsigned u = __float_as_uint(f);
    return (u & 0x80000000u) ? ~u : (u | 0x80000000u);
}
__device__ __forceinline__ float fkeyinv(unsigned k) {
    unsigned u = (k & 0x80000000u) ? (k & 0x7FFFFFFFu) : ~k;
    return __uint_as_float(u);
}

// ============================================================
// 1) copy em -> out[1..] (em_new initial state)
// ============================================================
__global__ void copy_kernel(const float* __restrict__ em, float* __restrict__ out) {
    size_t i = (size_t)blockIdx.x * blockDim.x + threadIdx.x;
    size_t stride = (size_t)gridDim.x * blockDim.x;
    const size_t n = (size_t)CM_ * D_;
    for (; i < n; i += stride) out[1 + i] = em[i];
}

// ============================================================
// 2) sims = inputs @ em^T  (fp32 SIMT tiled GEMM, 64x128x16 tile)
//    threads 256 = 16x16, per-thread 4x8 micro-tile
// ============================================================
__global__ void __launch_bounds__(256) gemm_kernel(const float* __restrict__ inp,
                                                   const float* __restrict__ em) {
    __shared__ float As[16][64];
    __shared__ float Bs[16][128];
    const int tid = threadIdx.x;
    const int tx = tid & 15;       // 0..15 -> n
    const int ty = tid >> 4;       // 0..15 -> m
    const int bm = blockIdx.y * 64;
    const int bn = blockIdx.x * 128;

    const int ia = tid >> 2;            // 0..63
    const int kq = (tid & 3) << 2;      // 0,4,8,12

    float acc[4][8];
    #pragma unroll
    for (int i = 0; i < 4; i++)
        #pragma unroll
        for (int j = 0; j < 8; j++) acc[i][j] = 0.f;

    for (int k0 = 0; k0 < D_; k0 += 16) {
        // A tile: 64 x 16
        {
            float4 av = *(const float4*)(inp + (size_t)(bm + ia) * D_ + k0 + kq);
            As[kq + 0][ia] = av.x; As[kq + 1][ia] = av.y;
            As[kq + 2][ia] = av.z; As[kq + 3][ia] = av.w;
        }
        // B tile: 128 x 16
        #pragma unroll
        for (int r = 0; r < 2; r++) {
            int jb = ia + r * 64;
            float4 bv = *(const float4*)(em + (size_t)(bn + jb) * D_ + k0 + kq);
            Bs[kq + 0][jb] = bv.x; Bs[kq + 1][jb] = bv.y;
            Bs[kq + 2][jb] = bv.z; Bs[kq + 3][jb] = bv.w;
        }
        __syncthreads();
        #pragma unroll
        for (int kk = 0; kk < 16; kk++) {
            float4 a  = *(const float4*)&As[kk][ty * 4];
            float4 b0 = *(const float4*)&Bs[kk][tx * 8];
            float4 b1 = *(const float4*)&Bs[kk][tx * 8 + 4];
            float av[4] = {a.x, a.y, a.z, a.w};
            float bv[8] = {b0.x, b0.y, b0.z, b0.w, b1.x, b1.y, b1.z, b1.w};
            #pragma unroll
            for (int i = 0; i < 4; i++)
                #pragma unroll
                for (int j = 0; j < 8; j++)
                    acc[i][j] = fmaf(av[i], bv[j], acc[i][j]);
        }
        __syncthreads();
    }
    #pragma unroll
    for (int i = 0; i < 4; i++) {
        float* dst = g_sims + (size_t)(bm + ty * 4 + i) * CM_ + bn + tx * 8;
        *(float4*)(dst)     = make_float4(acc[i][0], acc[i][1], acc[i][2], acc[i][3]);
        *(float4*)(dst + 4) = make_float4(acc[i][4], acc[i][5], acc[i][6], acc[i][7]);
    }
}

// ============================================================
// 3) per-sample loss: intra-cam CE + (epoch>=5) hard-negative term
//    one block per sample; row staged in 64KB dynamic smem
// ============================================================
__global__ void __launch_bounds__(256) loss_kernel(const int* __restrict__ targets,
                                                   const int* __restrict__ cams,
                                                   const int* __restrict__ ep) {
    extern __shared__ float srow[];       // CM_ floats
    __shared__ float spos[C_];
    const int b = blockIdx.x, tid = threadIdx.x;
    const int target = targets[b], cam = cams[b];
    const float* row = g_sims + (size_t)b * CM_;

    // stage row, mask the 8 positives (idx % M == target)
    for (int i = tid; i < CM_; i += 256) {
        float v = row[i];
        if ((i & (M_ - 1)) == target) v = -1000.f;
        srow[i] = v;
    }
    if (tid < C_) spos[tid] = row[tid * M_ + target];
    __syncthreads();

    // count of samples sharing my camera (blockDim == B_)
    float cnt = blockReduceSum((cams[tid] == cam) ? 1.f : 0.f);

    // ---- intra-camera CE over camera block ----
    float mx = -3.4e38f;
    for (int i = cam * M_ + tid; i < (cam + 1) * M_; i += 256) mx = fmaxf(mx, srow[i]);
    mx = fmaxf(mx, spos[cam]);            // true target value (masked in srow)
    mx = blockReduceMax(mx);
    float s = 0.f;
    for (int i = cam * M_ + tid; i < (cam + 1) * M_; i += 256)
        s += __expf((srow[i] - mx) * INVT);   // masked entry underflows to 0
    s = blockReduceSum(s);
    s += __expf((spos[cam] - mx) * INVT);
    float ce = mx * INVT + __logf(s) - spos[cam] * INVT;

    // ---- hard-negative associate loss ----
    int epoch = ep ? ep[0] : 6;
    float al = 0.f;
    if (epoch >= 5) {
        float gm = -3.4e38f;
        for (int i = tid; i < CM_; i += 256) gm = fmaxf(gm, srow[i]);
        gm = blockReduceMax(gm);

        // exact 50th-largest via binary search on monotone keys
        unsigned lo = 0u, hi = 0xFFFFFFFFu;
        while (lo < hi) {
            unsigned mid = (unsigned)((((unsigned long long)lo) + hi + 1ull) >> 1);
            float c = 0.f;
            for (int i = tid; i < CM_; i += 256)
                c += (fkey(srow[i]) >= mid) ? 1.f : 0.f;
            c = blockReduceSum(c);
            if (c >= (float)KNN) lo = mid; else hi = mid - 1u;
        }
        const unsigned k50 = lo;
        const float v50 = fkeyinv(k50);
        float cg = 0.f;
        for (int i = tid; i < CM_; i += 256)
            cg += (fkey(srow[i]) > k50) ? 1.f : 0.f;
        cg = blockReduceSum(cg);

        float pm = -3.4e38f, psum = 0.f;
        #pragma unroll
        for (int c2 = 0; c2 < C_; c2++) { pm = fmaxf(pm, spos[c2]); psum += spos[c2]; }
        const float m = fmaxf(gm, pm) * INVT;

        float sn = 0.f;
        for (int i = tid; i < CM_; i += 256) {
            float v = srow[i];
            if (fkey(v) > k50) sn += __expf(v * INVT - m);
        }
        sn = blockReduceSum(sn);
        sn += ((float)KNN - cg) * __expf(v50 * INVT - m);  // tie-correct

        float sp = 0.f;
        #pragma unroll
        for (int c2 = 0; c2 < C_; c2++) sp += __expf(spos[c2] * INVT - m);
        float lse = m + __logf(sp + sn);
        al = lse - psum * INVT / (float)C_;
    }

    if (tid == 0) g_partial[b] = (ce + 0.5f * al) / cnt;
}

// ============================================================
// 4) sequential-in-row EMA scatter + renorm. One block per sample;
//    only the first-occurrence block of a row owns the whole chain.
// ============================================================
__global__ void __launch_bounds__(256) ema_kernel(const float* __restrict__ inp,
                                                  const int* __restrict__ targets,
                                                  const int* __restrict__ cams,
                                                  float* __restrict__ em_out) {
    const int b = blockIdx.x, tid = threadIdx.x;
    const int r = cams[b] * M_ + targets[b];
    for (int bp = 0; bp < b; bp++)
        if (cams[bp] * M_ + targets[bp] == r) return;   // not the owner

    float v[8];
    const size_t base = (size_t)r * D_;
    #pragma unroll
    for (int j = 0; j < 8; j++) v[j] = em_out[base + j * 256 + tid];

    for (int bb = b; bb < B_; bb++) {
        if (cams[bb] * M_ + targets[bb] != r) continue;  // uniform across block
        float ss = 0.f;
        #pragma unroll
        for (int j = 0; j < 8; j++) {
            v[j] = 0.2f * v[j] + 0.8f * inp[(size_t)bb * D_ + j * 256 + tid];
            ss += v[j] * v[j];
        }
        ss = blockReduceSum(ss);
        float inv = rsqrtf(ss);
        #pragma unroll
        for (int j = 0; j < 8; j++) v[j] *= inv;
    }
    #pragma unroll
    for (int j = 0; j < 8; j++) em_out[base + j * 256 + tid] = v[j];
}

// ============================================================
// 5) deterministic final loss reduction
// ============================================================
__global__ void finish_kernel(float* __restrict__ out) {
    float v = (threadIdx.x < B_) ? g_partial[threadIdx.x] : 0.f;
    v = blockReduceSum(v);
    if (threadIdx.x == 0) out[0] = v;
}

// ============================================================
extern "C" void kernel_launch(void* const* d_in, const int* in_sizes, int n_in,
                              void* d_out, int out_size) {
    const float* inp     = (const float*)d_in[0];
    const float* em      = (const float*)d_in[1];
    const int*   targets = (const int*)d_in[2];
    const int*   cams    = (const int*)d_in[3];
    const int*   ep      = (n_in >= 5) ? (const int*)d_in[4] : nullptr;
    float* out = (float*)d_out;

    cudaFuncSetAttribute(loss_kernel, cudaFuncAttributeMaxDynamicSharedMemorySize, CM_ * 4);

    copy_kernel<<<2048, 256>>>(em, out);
    dim3 gg(CM_ / 128, B_ / 64);
    gemm_kernel<<<gg, 256>>>(inp, em);
    loss_kernel<<<B_, 256, CM_ * 4>>>(targets, cams, ep);
    ema_kernel<<<B_, 256>>>(inp, targets, cams, out + 1);
    finish_kernel<<<1, 256>>>(out);
}

// round 4
// speedup vs baseline: 3.4126x; 3.4126x over previous
#include <cuda_runtime.h>
#include <cstdint>

#define C_   8
#define M_   2048
#define D_   2048
#define B_   256
#define CM_  (C_ * M_)
#define KNN  50
#define INVT 20.0f   // 1/TEMP

// ---- scratch (device globals: allocation-free rule) ----
__device__ float g_sims[(size_t)B_ * CM_];   // 16 MB
__device__ float g_partial[B_];

// ============================================================
// helpers
// ============================================================
__device__ __forceinline__ uint32_t smem_u32(const void* p) {
    uint32_t a;
    asm("{ .reg .u64 t; cvta.to.shared.u64 t, %1; cvt.u32.u64 %0, t; }" : "=r"(a) : "l"(p));
    return a;
}
__device__ __forceinline__ uint32_t f2tf32(float f) {
    uint32_t u;
    asm("cvt.rna.tf32.f32 %0, %1;" : "=r"(u) : "f"(f));
    return u;
}
__device__ __forceinline__ void cp_async16(uint32_t dst, const void* src) {
    asm volatile("cp.async.cg.shared.global [%0], [%1], 16;" :: "r"(dst), "l"(src) : "memory");
}
#define CP_COMMIT() asm volatile("cp.async.commit_group;" ::: "memory")
#define CP_WAIT1()  asm volatile("cp.async.wait_group 1;" ::: "memory")

__device__ __forceinline__ void mma_tf32(float& d0, float& d1, float& d2, float& d3,
                                         uint32_t a0, uint32_t a1, uint32_t a2, uint32_t a3,
                                         uint32_t b0, uint32_t b1) {
    asm volatile(
        "mma.sync.aligned.m16n8k8.row.col.f32.tf32.tf32.f32 "
        "{%0,%1,%2,%3}, {%4,%5,%6,%7}, {%8,%9}, {%0,%1,%2,%3};"
        : "+f"(d0), "+f"(d1), "+f"(d2), "+f"(d3)
        : "r"(a0), "r"(a1), "r"(a2), "r"(a3), "r"(b0), "r"(b1));
}

// ============================================================
// block reductions (256-thread blocks)
// ============================================================
__device__ __forceinline__ float blockReduceSum(float val) {
    __shared__ float sh[32];
    int lane = threadIdx.x & 31, wid = threadIdx.x >> 5;
    #pragma unroll
    for (int o = 16; o; o >>= 1) val += __shfl_down_sync(0xffffffffu, val, o);
    if (lane == 0) sh[wid] = val;
    __syncthreads();
    int nw = (blockDim.x + 31) >> 5;
    val = (threadIdx.x < (unsigned)nw) ? sh[threadIdx.x] : 0.f;
    if (wid == 0) {
        #pragma unroll
        for (int o = 16; o; o >>= 1) val += __shfl_down_sync(0xffffffffu, val, o);
        if (lane == 0) sh[0] = val;
    }
    __syncthreads();
    val = sh[0];
    __syncthreads();
    return val;
}
__device__ __forceinline__ float blockReduceMax(float val) {
    __shared__ float sh[32];
    int lane = threadIdx.x & 31, wid = threadIdx.x >> 5;
    #pragma unroll
    for (int o = 16; o; o >>= 1) val = fmaxf(val, __shfl_down_sync(0xffffffffu, val, o));
    if (lane == 0) sh[wid] = val;
    __syncthreads();
    int nw = (blockDim.x + 31) >> 5;
    val = (threadIdx.x < (unsigned)nw) ? sh[threadIdx.x] : -3.4e38f;
    if (wid == 0) {
        #pragma unroll
        for (int o = 16; o; o >>= 1) val = fmaxf(val, __shfl_down_sync(0xffffffffu, val, o));
        if (lane == 0) sh[0] = val;
    }
    __syncthreads();
    val = sh[0];
    __syncthreads();
    return val;
}
__device__ __forceinline__ unsigned fkey(float f) {
    unsigned u = __float_as_uint(f);
    return (u & 0x80000000u) ? ~u : (u | 0x80000000u);
}
__device__ __forceinline__ float fkeyinv(unsigned k) {
    unsigned u = (k & 0x80000000u) ? (k & 0x7FFFFFFFu) : ~k;
    return __uint_as_float(u);
}

// ============================================================
// 1) copy em -> out[1..]
// ============================================================
__global__ void copy_kernel(const float* __restrict__ em, float* __restrict__ out) {
    size_t i = (size_t)blockIdx.x * blockDim.x + threadIdx.x;
    size_t stride = (size_t)gridDim.x * blockDim.x;
    const size_t n = (size_t)CM_ * D_;
    for (; i < n; i += stride) out[1 + i] = __ldg(em + i);
}

// ============================================================
// 2) tf32 mma.sync GEMM: g_sims[256, 16384] = inputs @ em^T
//    CTA tile 128(M) x 128(N), BK=32, 8 warps (2x4), warp tile 64x32.
//    cp.async double-buffered smem; stride-36 padding -> conflict-free
//    scalar frag LDS. cvt.rna.tf32 on frag load.
// ============================================================
#define BK      32
#define NCHUNK  (D_ / BK)                 // 64
#define TSTRIDE 36                        // floats per row (32 + 4 pad)
#define TILE_F  (128 * TSTRIDE)           // 4608 floats = 18432 B
#define GEMM_SMEM (4 * TILE_F * 4)        // A0,B0,A1,B1 = 73728 B

__global__ void __launch_bounds__(256, 2) gemm_mma_kernel(const float* __restrict__ inp,
                                                          const float* __restrict__ em) {
    extern __shared__ float smem[];
    const int tid  = threadIdx.x;
    const int lane = tid & 31;
    const int wid  = tid >> 5;
    const int wm   = wid >> 2;            // 0..1 -> 64 M rows
    const int wn   = wid & 3;             // 0..3 -> 32 N cols
    const int bm   = blockIdx.y * 128;
    const int bn   = blockIdx.x * 128;

    const uint32_t sb = smem_u32(smem);

    // per-thread cp.async assignment (same pattern for A and B)
    int rowi[4], segi[4];
    #pragma unroll
    for (int i = 0; i < 4; i++) {
        int idx = i * 256 + tid;          // 0..1023
        rowi[i] = idx >> 3;               // 0..127
        segi[i] = idx & 7;                // 0..7 (float4 seg)
    }

    auto issue_chunk = [&](int k, int b) {
        const int k0 = k * BK;
        const uint32_t abase = sb + (uint32_t)(b * 2) * (TILE_F * 4);
        const uint32_t bbase = sb + (uint32_t)(b * 2 + 1) * (TILE_F * 4);
        #pragma unroll
        for (int i = 0; i < 4; i++) {
            const int row = rowi[i], seg = segi[i];
            const uint32_t soff = (uint32_t)(row * (TSTRIDE * 4) + seg * 16);
            cp_async16(abase + soff, inp + (size_t)(bm + row) * D_ + k0 + seg * 4);
            cp_async16(bbase + soff, em  + (size_t)(bn + row) * D_ + k0 + seg * 4);
        }
        CP_COMMIT();
    };

    float acc[4][4][4];
    #pragma unroll
    for (int mi = 0; mi < 4; mi++)
        #pragma unroll
        for (int ni = 0; ni < 4; ni++)
            #pragma unroll
            for (int j = 0; j < 4; j++) acc[mi][ni][j] = 0.f;

    issue_chunk(0, 0);
    issue_chunk(1, 1);
    CP_WAIT1();
    __syncthreads();

    for (int k = 0; k < NCHUNK; k++) {
        const int b = k & 1;
        const float* As = smem + (b * 2)     * TILE_F;
        const float* Bs = smem + (b * 2 + 1) * TILE_F;

        #pragma unroll
        for (int kk = 0; kk < BK; kk += 8) {
            uint32_t af[4][4], bf[4][2];
            #pragma unroll
            for (int mi = 0; mi < 4; mi++) {
                const int r = wm * 64 + mi * 16 + (lane >> 2);
                const int c = kk + (lane & 3);
                af[mi][0] = f2tf32(As[r * TSTRIDE + c]);
                af[mi][1] = f2tf32(As[(r + 8) * TSTRIDE + c]);
                af[mi][2] = f2tf32(As[r * TSTRIDE + c + 4]);
                af[mi][3] = f2tf32(As[(r + 8) * TSTRIDE + c + 4]);
            }
            #pragma unroll
            for (int ni = 0; ni < 4; ni++) {
                const int n = wn * 32 + ni * 8 + (lane >> 2);
                const int c = kk + (lane & 3);
                bf[ni][0] = f2tf32(Bs[n * TSTRIDE + c]);
                bf[ni][1] = f2tf32(Bs[n * TSTRIDE + c + 4]);
            }
            #pragma unroll
            for (int mi = 0; mi < 4; mi++)
                #pragma unroll
                for (int ni = 0; ni < 4; ni++)
                    mma_tf32(acc[mi][ni][0], acc[mi][ni][1], acc[mi][ni][2], acc[mi][ni][3],
                             af[mi][0], af[mi][1], af[mi][2], af[mi][3],
                             bf[ni][0], bf[ni][1]);
        }

        __syncthreads();
        if (k + 2 < NCHUNK) issue_chunk(k + 2, b);
        else CP_COMMIT();                 // keep group count uniform
        CP_WAIT1();
        __syncthreads();
    }

    // epilogue
    #pragma unroll
    for (int mi = 0; mi < 4; mi++) {
        const int r0 = bm + wm * 64 + mi * 16 + (lane >> 2);
        #pragma unroll
        for (int ni = 0; ni < 4; ni++) {
            const int c = bn + wn * 32 + ni * 8 + (lane & 3) * 2;
            *(float2*)(g_sims + (size_t)r0 * CM_ + c)       = make_float2(acc[mi][ni][0], acc[mi][ni][1]);
            *(float2*)(g_sims + (size_t)(r0 + 8) * CM_ + c) = make_float2(acc[mi][ni][2], acc[mi][ni][3]);
        }
    }
}

// ============================================================
// 3) per-sample loss
// ============================================================
__global__ void __launch_bounds__(256) loss_kernel(const int* __restrict__ targets,
                                                   const int* __restrict__ cams,
                                                   const int* __restrict__ ep) {
    extern __shared__ float srow[];       // CM_ floats
    __shared__ float spos[C_];
    const int b = blockIdx.x, tid = threadIdx.x;
    const int target = targets[b], cam = cams[b];
    const float* row = g_sims + (size_t)b * CM_;

    for (int i = tid; i < CM_; i += 256) {
        float v = row[i];
        if ((i & (M_ - 1)) == target) v = -1000.f;
        srow[i] = v;
    }
    if (tid < C_) spos[tid] = row[tid * M_ + target];
    __syncthreads();

    float cnt = blockReduceSum((cams[tid] == cam) ? 1.f : 0.f);

    float mx = -3.4e38f;
    for (int i = cam * M_ + tid; i < (cam + 1) * M_; i += 256) mx = fmaxf(mx, srow[i]);
    mx = fmaxf(mx, spos[cam]);
    mx = blockReduceMax(mx);
    float s = 0.f;
    for (int i = cam * M_ + tid; i < (cam + 1) * M_; i += 256)
        s += __expf((srow[i] - mx) * INVT);
    s = blockReduceSum(s);
    s += __expf((spos[cam] - mx) * INVT);
    float ce = mx * INVT + __logf(s) - spos[cam] * INVT;

    int epoch = ep ? ep[0] : 6;
    float al = 0.f;
    if (epoch >= 5) {
        float gm = -3.4e38f;
        for (int i = tid; i < CM_; i += 256) gm = fmaxf(gm, srow[i]);
        gm = blockReduceMax(gm);

        unsigned lo = 0u, hi = 0xFFFFFFFFu;
        while (lo < hi) {
            unsigned mid = (unsigned)((((unsigned long long)lo) + hi + 1ull) >> 1);
            float c = 0.f;
            for (int i = tid; i < CM_; i += 256)
                c += (fkey(srow[i]) >= mid) ? 1.f : 0.f;
            c = blockReduceSum(c);
            if (c >= (float)KNN) lo = mid; else hi = mid - 1u;
        }
        const unsigned k50 = lo;
        const float v50 = fkeyinv(k50);
        float cg = 0.f;
        for (int i = tid; i < CM_; i += 256)
            cg += (fkey(srow[i]) > k50) ? 1.f : 0.f;
        cg = blockReduceSum(cg);

        float pm = -3.4e38f, psum = 0.f;
        #pragma unroll
        for (int c2 = 0; c2 < C_; c2++) { pm = fmaxf(pm, spos[c2]); psum += spos[c2]; }
        const float m = fmaxf(gm, pm) * INVT;

        float sn = 0.f;
        for (int i = tid; i < CM_; i += 256) {
            float v = srow[i];
            if (fkey(v) > k50) sn += __expf(v * INVT - m);
        }
        sn = blockReduceSum(sn);
        sn += ((float)KNN - cg) * __expf(v50 * INVT - m);

        float sp = 0.f;
        #pragma unroll
        for (int c2 = 0; c2 < C_; c2++) sp += __expf(spos[c2] * INVT - m);
        float lse = m + __logf(sp + sn);
        al = lse - psum * INVT / (float)C_;
    }

    if (tid == 0) g_partial[b] = (ce + 0.5f * al) / cnt;
}

// ============================================================
// 4) sequential-in-row EMA scatter + renorm
// ============================================================
__global__ void __launch_bounds__(256) ema_kernel(const float* __restrict__ inp,
                                                  const int* __restrict__ targets,
                                                  const int* __restrict__ cams,
                                                  float* __restrict__ em_out) {
    __shared__ int srid[B_];
    const int b = blockIdx.x, tid = threadIdx.x;
    srid[tid] = cams[tid] * M_ + targets[tid];
    __syncthreads();
    const int r = srid[b];
    for (int bp = 0; bp < b; bp++)
        if (srid[bp] == r) return;   // not the owner

    float v[8];
    const size_t base = (size_t)r * D_ + tid * 8;
    #pragma unroll
    for (int j = 0; j < 8; j++) v[j] = em_out[base + j];

    for (int bb = b; bb < B_; bb++) {
        if (srid[bb] != r) continue;
        const float4* ip = (const float4*)(inp + (size_t)bb * D_ + tid * 8);
        float4 i0 = ip[0], i1 = ip[1];
        float xv[8] = {i0.x, i0.y, i0.z, i0.w, i1.x, i1.y, i1.z, i1.w};
        float ss = 0.f;
        #pragma unroll
        for (int j = 0; j < 8; j++) {
            v[j] = 0.2f * v[j] + 0.8f * xv[j];
            ss += v[j] * v[j];
        }
        ss = blockReduceSum(ss);
        float inv = rsqrtf(ss);
        #pragma unroll
        for (int j = 0; j < 8; j++) v[j] *= inv;
    }
    #pragma unroll
    for (int j = 0; j < 8; j++) em_out[base + j] = v[j];
}

// ============================================================
// 5) final loss reduction
// ============================================================
__global__ void finish_kernel(float* __restrict__ out) {
    float v = (threadIdx.x < B_) ? g_partial[threadIdx.x] : 0.f;
    v = blockReduceSum(v);
    if (threadIdx.x == 0) out[0] = v;
}

// ============================================================
extern "C" void kernel_launch(void* const* d_in, const int* in_sizes, int n_in,
                              void* d_out, int out_size) {
    const float* inp     = (const float*)d_in[0];
    const float* em      = (const float*)d_in[1];
    const int*   targets = (const int*)d_in[2];
    const int*   cams    = (const int*)d_in[3];
    const int*   ep      = (n_in >= 5) ? (const int*)d_in[4] : nullptr;
    float* out = (float*)d_out;

    cudaFuncSetAttribute(loss_kernel, cudaFuncAttributeMaxDynamicSharedMemorySize, CM_ * 4);
    cudaFuncSetAttribute(gemm_mma_kernel, cudaFuncAttributeMaxDynamicSharedMemorySize, GEMM_SMEM);

    copy_kernel<<<2048, 256>>>(em, out);
    dim3 gg(CM_ / 128, B_ / 128);
    gemm_mma_kernel<<<gg, 256, GEMM_SMEM>>>(inp, em);
    loss_kernel<<<B_, 256, CM_ * 4>>>(targets, cams, ep);
    ema_kernel<<<B_, 256>>>(inp, targets, cams, out + 1);
    finish_kernel<<<1, 256>>>(out);
}

// round 6
// speedup vs baseline: 4.0570x; 1.1888x over previous
#include <cuda_runtime.h>
#include <cstdint>

#define C_   8
#define M_   2048
#define D_   2048
#define B_   256
#define CM_  (C_ * M_)
#define KNN  50
#define INVT 20.0f   // 1/TEMP

// ---- scratch (device globals: allocation-free rule) ----
__device__ float g_sims[(size_t)B_ * CM_];   // 16 MB
__device__ float g_partial[B_];

// ============================================================
// helpers
// ============================================================
__device__ __forceinline__ uint32_t smem_u32(const void* p) {
    uint32_t a;
    asm("{ .reg .u64 t; cvta.to.shared.u64 t, %1; cvt.u32.u64 %0, t; }" : "=r"(a) : "l"(p));
    return a;
}
__device__ __forceinline__ uint32_t f2tf32(float f) {
    uint32_t u;
    asm("cvt.rna.tf32.f32 %0, %1;" : "=r"(u) : "f"(f));
    return u;
}
__device__ __forceinline__ void cp_async16(uint32_t dst, const void* src) {
    asm volatile("cp.async.cg.shared.global [%0], [%1], 16;" :: "r"(dst), "l"(src) : "memory");
}
#define CP_COMMIT() asm volatile("cp.async.commit_group;" ::: "memory")
#define CP_WAIT1()  asm volatile("cp.async.wait_group 1;" ::: "memory")

__device__ __forceinline__ void mma_tf32(float& d0, float& d1, float& d2, float& d3,
                                         uint32_t a0, uint32_t a1, uint32_t a2, uint32_t a3,
                                         uint32_t b0, uint32_t b1) {
    asm volatile(
        "mma.sync.aligned.m16n8k8.row.col.f32.tf32.tf32.f32 "
        "{%0,%1,%2,%3}, {%4,%5,%6,%7}, {%8,%9}, {%0,%1,%2,%3};"
        : "+f"(d0), "+f"(d1), "+f"(d2), "+f"(d3)
        : "r"(a0), "r"(a1), "r"(a2), "r"(a3), "r"(b0), "r"(b1));
}

// ============================================================
// block reductions (256-thread blocks)
// ============================================================
__device__ __forceinline__ float blockReduceSum(float val) {
    __shared__ float sh[32];
    int lane = threadIdx.x & 31, wid = threadIdx.x >> 5;
    #pragma unroll
    for (int o = 16; o; o >>= 1) val += __shfl_down_sync(0xffffffffu, val, o);
    if (lane == 0) sh[wid] = val;
    __syncthreads();
    int nw = (blockDim.x + 31) >> 5;
    val = (threadIdx.x < (unsigned)nw) ? sh[threadIdx.x] : 0.f;
    if (wid == 0) {
        #pragma unroll
        for (int o = 16; o; o >>= 1) val += __shfl_down_sync(0xffffffffu, val, o);
        if (lane == 0) sh[0] = val;
    }
    __syncthreads();
    val = sh[0];
    __syncthreads();
    return val;
}
__device__ __forceinline__ float blockReduceMax(float val) {
    __shared__ float sh[32];
    int lane = threadIdx.x & 31, wid = threadIdx.x >> 5;
    #pragma unroll
    for (int o = 16; o; o >>= 1) val = fmaxf(val, __shfl_down_sync(0xffffffffu, val, o));
    if (lane == 0) sh[wid] = val;
    __syncthreads();
    int nw = (blockDim.x + 31) >> 5;
    val = (threadIdx.x < (unsigned)nw) ? sh[threadIdx.x] : -3.4e38f;
    if (wid == 0) {
        #pragma unroll
        for (int o = 16; o; o >>= 1) val = fmaxf(val, __shfl_down_sync(0xffffffffu, val, o));
        if (lane == 0) sh[0] = val;
    }
    __syncthreads();
    val = sh[0];
    __syncthreads();
    return val;
}
__device__ __forceinline__ unsigned fkey(float f) {
    unsigned u = __float_as_uint(f);
    return (u & 0x80000000u) ? ~u : (u | 0x80000000u);
}
__device__ __forceinline__ float fkeyinv(unsigned k) {
    unsigned u = (k & 0x80000000u) ? (k & 0x7FFFFFFFu) : ~k;
    return __uint_as_float(u);
}

// ============================================================
// 1) tf32 mma.sync GEMM + fused em copy:
//    g_sims[256, 16384] = inputs @ em^T, and out_em[...] = em.
//    CTA tile 128(M) x 128(N), BK=32, 8 warps (2x4), warp tile 64x32.
//    cp.async double buffer; in-place RNA tf32 conversion per tile.
//    B-tile write-through to out_em uses SCALAR stores: out_em = out+1
//    is only 4-byte aligned (float4 stores trap).
// ============================================================
#define BK      32
#define NCHUNK  (D_ / BK)                 // 64
#define TSTRIDE 36                        // floats per row (32 + 4 pad)
#define TILE_F  (128 * TSTRIDE)           // 4608 floats
#define GEMM_SMEM (4 * TILE_F * 4)        // 73728 B

__global__ void __launch_bounds__(256, 2) gemm_mma_kernel(const float* __restrict__ inp,
                                                          const float* __restrict__ em,
                                                          float* __restrict__ out_em) {
    extern __shared__ float smem[];
    const int tid  = threadIdx.x;
    const int lane = tid & 31;
    const int wid  = tid >> 5;
    const int wm   = wid >> 2;            // 0..1 -> 64 M rows
    const int wn   = wid & 3;             // 0..3 -> 32 N cols
    const int bm   = blockIdx.y * 128;
    const int bmid = blockIdx.y;          // 0 or 1
    const int bn   = blockIdx.x * 128;

    const uint32_t sb = smem_u32(smem);

    int rowi[4], segi[4];
    #pragma unroll
    for (int i = 0; i < 4; i++) {
        int idx = i * 256 + tid;          // 0..1023
        rowi[i] = idx >> 3;               // 0..127
        segi[i] = idx & 7;                // 0..7
    }

    auto issue_chunk = [&](int k, int b) {
        const int k0 = k * BK;
        const uint32_t abase = sb + (uint32_t)(b * 2) * (TILE_F * 4);
        const uint32_t bbase = sb + (uint32_t)(b * 2 + 1) * (TILE_F * 4);
        #pragma unroll
        for (int i = 0; i < 4; i++) {
            const int row = rowi[i], seg = segi[i];
            const uint32_t soff = (uint32_t)(row * (TSTRIDE * 4) + seg * 16);
            cp_async16(abase + soff, inp + (size_t)(bm + row) * D_ + k0 + seg * 4);
            cp_async16(bbase + soff, em  + (size_t)(bn + row) * D_ + k0 + seg * 4);
        }
        CP_COMMIT();
    };

    float acc[4][4][4];
    #pragma unroll
    for (int mi = 0; mi < 4; mi++)
        #pragma unroll
        for (int ni = 0; ni < 4; ni++)
            #pragma unroll
            for (int j = 0; j < 4; j++) acc[mi][ni][j] = 0.f;

    issue_chunk(0, 0);
    issue_chunk(1, 1);
    CP_WAIT1();
    __syncthreads();

    for (int k = 0; k < NCHUNK; k++) {
        const int b = k & 1;
        float* As = smem + (b * 2)     * TILE_F;
        float* Bs = smem + (b * 2 + 1) * TILE_F;
        const int k0 = k * BK;
        const bool do_copy = ((k >> 5) == bmid);

        // in-place tf32(RNA) conversion + scalar write-through em copy
        #pragma unroll
        for (int i = 0; i < 4; i++) {
            const int row = rowi[i], seg = segi[i];
            const int so = row * TSTRIDE + seg * 4;
            float4 ra = *(float4*)(As + so);
            float4 rb = *(float4*)(Bs + so);
            if (do_copy) {
                float* d = out_em + (size_t)(bn + row) * D_ + k0 + seg * 4;
                d[0] = rb.x; d[1] = rb.y; d[2] = rb.z; d[3] = rb.w;   // 4-byte-aligned base: scalar only
            }
            *(uint4*)(As + so) = make_uint4(f2tf32(ra.x), f2tf32(ra.y), f2tf32(ra.z), f2tf32(ra.w));
            *(uint4*)(Bs + so) = make_uint4(f2tf32(rb.x), f2tf32(rb.y), f2tf32(rb.z), f2tf32(rb.w));
        }
        __syncthreads();

        const uint32_t* Au = (const uint32_t*)As;
        const uint32_t* Bu = (const uint32_t*)Bs;
        #pragma unroll
        for (int kk = 0; kk < BK; kk += 8) {
            uint32_t af[4][4], bf[4][2];
            #pragma unroll
            for (int mi = 0; mi < 4; mi++) {
                const int r = wm * 64 + mi * 16 + (lane >> 2);
                const int c = kk + (lane & 3);
                af[mi][0] = Au[r * TSTRIDE + c];
                af[mi][1] = Au[(r + 8) * TSTRIDE + c];
                af[mi][2] = Au[r * TSTRIDE + c + 4];
                af[mi][3] = Au[(r + 8) * TSTRIDE + c + 4];
            }
            #pragma unroll
            for (int ni = 0; ni < 4; ni++) {
                const int n = wn * 32 + ni * 8 + (lane >> 2);
                const int c = kk + (lane & 3);
                bf[ni][0] = Bu[n * TSTRIDE + c];
                bf[ni][1] = Bu[n * TSTRIDE + c + 4];
            }
            #pragma unroll
            for (int mi = 0; mi < 4; mi++)
                #pragma unroll
                for (int ni = 0; ni < 4; ni++)
                    mma_tf32(acc[mi][ni][0], acc[mi][ni][1], acc[mi][ni][2], acc[mi][ni][3],
                             af[mi][0], af[mi][1], af[mi][2], af[mi][3],
                             bf[ni][0], bf[ni][1]);
        }

        __syncthreads();
        if (k + 2 < NCHUNK) issue_chunk(k + 2, b);
        else CP_COMMIT();                 // keep group count uniform
        CP_WAIT1();
        __syncthreads();
    }

    // epilogue (g_sims is a 16B-aligned device global: float2 OK)
    #pragma unroll
    for (int mi = 0; mi < 4; mi++) {
        const int r0 = bm + wm * 64 + mi * 16 + (lane >> 2);
        #pragma unroll
        for (int ni = 0; ni < 4; ni++) {
            const int c = bn + wn * 32 + ni * 8 + (lane & 3) * 2;
            *(float2*)(g_sims + (size_t)r0 * CM_ + c)       = make_float2(acc[mi][ni][0], acc[mi][ni][1]);
            *(float2*)(g_sims + (size_t)(r0 + 8) * CM_ + c) = make_float2(acc[mi][ni][2], acc[mi][ni][3]);
        }
    }
}

// ============================================================
// 2) per-sample loss: CE + hard-negative term.
//    Top-50 via 2048-bin histogram + candidate compaction (exact,
//    with in-bin binary-search fallback on overflow).
// ============================================================
#define NBIN  2048
#define CAP   768
#define LOSS_SMEM (CM_ * 4 + NBIN * 4 + CAP * 4)

__global__ void __launch_bounds__(256) loss_kernel(const int* __restrict__ targets,
                                                   const int* __restrict__ cams,
                                                   const int* __restrict__ ep) {
    extern __shared__ float srow[];                       // CM_ floats
    unsigned* hist = (unsigned*)(srow + CM_);             // NBIN
    unsigned* buf  = hist + NBIN;                         // CAP
    __shared__ float spos[C_];
    __shared__ unsigned chunksum[256];
    __shared__ int s_tb;
    __shared__ unsigned s_cumhi, s_cnt;

    const int b = blockIdx.x, tid = threadIdx.x;
    const int target = targets[b], cam = cams[b];
    const float* row = g_sims + (size_t)b * CM_;

    for (int i = tid; i < NBIN; i += 256) hist[i] = 0;
    if (tid == 0) s_cnt = 0;
    for (int i = tid; i < CM_; i += 256) {
        float v = row[i];
        if ((i & (M_ - 1)) == target) v = -1000.f;
        srow[i] = v;
    }
    if (tid < C_) spos[tid] = row[tid * M_ + target];
    __syncthreads();

    float cnt = blockReduceSum((cams[tid] == cam) ? 1.f : 0.f);

    // ---- intra-camera CE ----
    float mx = -3.4e38f;
    for (int i = cam * M_ + tid; i < (cam + 1) * M_; i += 256) mx = fmaxf(mx, srow[i]);
    mx = fmaxf(mx, spos[cam]);
    mx = blockReduceMax(mx);
    float s = 0.f;
    for (int i = cam * M_ + tid; i < (cam + 1) * M_; i += 256)
        s += __expf((srow[i] - mx) * INVT);
    s = blockReduceSum(s);
    s += __expf((spos[cam] - mx) * INVT);
    float ce = mx * INVT + __logf(s) - spos[cam] * INVT;

    // ---- hard-negative associate loss ----
    int epoch = ep ? ep[0] : 6;
    float al = 0.f;
    if (epoch >= 5) {
        // one sweep: global max + histogram of fkey >> 21
        float gm = -3.4e38f;
        for (int i = tid; i < CM_; i += 256) {
            float v = srow[i];
            gm = fmaxf(gm, v);
            atomicAdd(&hist[fkey(v) >> 21], 1u);
        }
        gm = blockReduceMax(gm);   // contains syncthreads -> hist complete

        // descending chunk sums: thread t covers bins [NBIN-8(t+1), NBIN-8t)
        const int base = NBIN - 8 * (tid + 1);
        unsigned s8 = 0;
        #pragma unroll
        for (int j = 0; j < 8; j++) s8 += hist[base + j];
        chunksum[tid] = s8;
        __syncthreads();
        for (int off = 1; off < 256; off <<= 1) {
            unsigned v = (tid >= off) ? chunksum[tid - off] : 0u;
            __syncthreads();
            chunksum[tid] += v;
            __syncthreads();
        }
        unsigned excl = (tid == 0) ? 0u : chunksum[tid - 1];
        if (excl < (unsigned)KNN && chunksum[tid] >= (unsigned)KNN) {
            unsigned c = excl;
            for (int j = 7; j >= 0; j--) {
                unsigned h = hist[base + j];
                if (c + h >= (unsigned)KNN) { s_tb = base + j; s_cumhi = c; break; }
                c += h;
            }
        }
        __syncthreads();
        const unsigned kT = ((unsigned)s_tb) << 21;
        const unsigned cand = s_cumhi + hist[s_tb];

        unsigned k50;
        float cg, sn;

        float pm = -3.4e38f, psum = 0.f;
        #pragma unroll
        for (int c2 = 0; c2 < C_; c2++) { pm = fmaxf(pm, spos[c2]); psum += spos[c2]; }
        const float mm = fmaxf(gm, pm) * INVT;

        if (cand <= (unsigned)CAP) {
            // compact candidates (keys >= kT); exactly `cand` entries
            for (int i = tid; i < CM_; i += 256) {
                unsigned k = fkey(srow[i]);
                if (k >= kT) { unsigned p = atomicAdd(&s_cnt, 1u); buf[p] = k; }
            }
            __syncthreads();
            const int S = (int)s_cnt;
            unsigned lo = kT, hi = fkey(gm);
            while (lo < hi) {
                unsigned mid = (unsigned)((((unsigned long long)lo) + hi + 1ull) >> 1);
                float c = 0.f;
                for (int i = tid; i < S; i += 256) c += (buf[i] >= mid) ? 1.f : 0.f;
                c = blockReduceSum(c);
                if (c >= (float)KNN) lo = mid; else hi = mid - 1u;
            }
            k50 = lo;
            float cgl = 0.f, snl = 0.f;
            for (int i = tid; i < S; i += 256) {
                unsigned k = buf[i];
                if (k > k50) {
                    cgl += 1.f;
                    snl += __expf(fkeyinv(k) * INVT - mm);
                }
            }
            cg = blockReduceSum(cgl);
            sn = blockReduceSum(snl);
        } else {
            // fallback: binary search within bin tb over the full row
            unsigned lo = kT, hi = kT + (1u << 21) - 1u;
            while (lo < hi) {
                unsigned mid = (unsigned)((((unsigned long long)lo) + hi + 1ull) >> 1);
                float c = 0.f;
                for (int i = tid; i < CM_; i += 256)
                    c += (fkey(srow[i]) >= mid) ? 1.f : 0.f;
                c = blockReduceSum(c);
                if (c >= (float)KNN) lo = mid; else hi = mid - 1u;
            }
            k50 = lo;
            float cgl = 0.f, snl = 0.f;
            for (int i = tid; i < CM_; i += 256) {
                float v = srow[i];
                if (fkey(v) > k50) {
                    cgl += 1.f;
                    snl += __expf(v * INVT - mm);
                }
            }
            cg = blockReduceSum(cgl);
            sn = blockReduceSum(snl);
        }

        const float v50 = fkeyinv(k50);
        sn += ((float)KNN - cg) * __expf(v50 * INVT - mm);   // tie-correct

        float sp = 0.f;
        #pragma unroll
        for (int c2 = 0; c2 < C_; c2++) sp += __expf(spos[c2] * INVT - mm);
        float lse = mm + __logf(sp + sn);
        al = lse - psum * INVT / (float)C_;
    }

    if (tid == 0) g_partial[b] = (ce + 0.5f * al) / cnt;
}

// ============================================================
// 3) sequential-in-row EMA scatter + renorm (scalar em_out access:
//    out+1 is 4-byte aligned)
// ============================================================
__global__ void __launch_bounds__(256) ema_kernel(const float* __restrict__ inp,
                                                  const int* __restrict__ targets,
                                                  const int* __restrict__ cams,
                                                  float* __restrict__ em_out) {
    __shared__ int srid[B_];
    const int b = blockIdx.x, tid = threadIdx.x;
    srid[tid] = cams[tid] * M_ + targets[tid];
    __syncthreads();
    const int r = srid[b];
    for (int bp = 0; bp < b; bp++)
        if (srid[bp] == r) return;   // not the owner

    float v[8];
    const size_t base = (size_t)r * D_ + tid * 8;
    #pragma unroll
    for (int j = 0; j < 8; j++) v[j] = em_out[base + j];

    for (int bb = b; bb < B_; bb++) {
        if (srid[bb] != r) continue;
        const float4* ip = (const float4*)(inp + (size_t)bb * D_ + tid * 8);
        float4 i0 = ip[0], i1 = ip[1];
        float xv[8] = {i0.x, i0.y, i0.z, i0.w, i1.x, i1.y, i1.z, i1.w};
        float ss = 0.f;
        #pragma unroll
        for (int j = 0; j < 8; j++) {
            v[j] = 0.2f * v[j] + 0.8f * xv[j];
            ss += v[j] * v[j];
        }
        ss = blockReduceSum(ss);
        float inv = rsqrtf(ss);
        #pragma unroll
        for (int j = 0; j < 8; j++) v[j] *= inv;
    }
    #pragma unroll
    for (int j = 0; j < 8; j++) em_out[base + j] = v[j];
}

// ============================================================
// 4) final loss reduction
// ============================================================
__global__ void finish_kernel(float* __restrict__ out) {
    float v = (threadIdx.x < B_) ? g_partial[threadIdx.x] : 0.f;
    v = blockReduceSum(v);
    if (threadIdx.x == 0) out[0] = v;
}

// ============================================================
extern "C" void kernel_launch(void* const* d_in, const int* in_sizes, int n_in,
                              void* d_out, int out_size) {
    const float* inp     = (const float*)d_in[0];
    const float* em      = (const float*)d_in[1];
    const int*   targets = (const int*)d_in[2];
    const int*   cams    = (const int*)d_in[3];
    const int*   ep      = (n_in >= 5) ? (const int*)d_in[4] : nullptr;
    float* out = (float*)d_out;

    cudaFuncSetAttribute(loss_kernel, cudaFuncAttributeMaxDynamicSharedMemorySize, LOSS_SMEM);
    cudaFuncSetAttribute(gemm_mma_kernel, cudaFuncAttributeMaxDynamicSharedMemorySize, GEMM_SMEM);

    dim3 gg(CM_ / 128, B_ / 128);
    gemm_mma_kernel<<<gg, 256, GEMM_SMEM>>>(inp, em, out + 1);
    loss_kernel<<<B_, 256, LOSS_SMEM>>>(targets, cams, ep);
    ema_kernel<<<B_, 256>>>(inp, targets, cams, out + 1);
    finish_kernel<<<1, 256>>>(out);
}

// round 9
// speedup vs baseline: 4.8472x; 1.1948x over previous
#include <cuda_runtime.h>
#include <cstdint>

#define C_   8
#define M_   2048
#define D_   2048
#define B_   256
#define CM_  (C_ * M_)
#define KNN  50
#define INVT 20.0f   // 1/TEMP

// ---- scratch (device globals: allocation-free rule) ----
__device__ float g_sims[(size_t)B_ * CM_];   // 16 MB
__device__ float g_partial[B_];

// ============================================================
// helpers
// ============================================================
__device__ __forceinline__ uint32_t smem_u32(const void* p) {
    uint32_t a;
    asm("{ .reg .u64 t; cvta.to.shared.u64 t, %1; cvt.u32.u64 %0, t; }" : "=r"(a) : "l"(p));
    return a;
}
__device__ __forceinline__ uint32_t pk_bf16(float lo, float hi) {
    uint32_t r;
    asm("cvt.rn.bf16x2.f32 %0, %1, %2;" : "=r"(r) : "f"(hi), "f"(lo));   // d.hi=%1, d.lo=%2
    return r;
}
__device__ __forceinline__ void cp_async16(uint32_t dst, const void* src) {
    asm volatile("cp.async.cg.shared.global [%0], [%1], 16;" :: "r"(dst), "l"(src) : "memory");
}
#define CP_COMMIT() asm volatile("cp.async.commit_group;" ::: "memory")
#define CP_WAIT1()  asm volatile("cp.async.wait_group 1;" ::: "memory")

__device__ __forceinline__ void mma_bf16(float& d0, float& d1, float& d2, float& d3,
                                         uint32_t a0, uint32_t a1, uint32_t a2, uint32_t a3,
                                         uint32_t b0, uint32_t b1) {
    asm volatile(
        "mma.sync.aligned.m16n8k16.row.col.f32.bf16.bf16.f32 "
        "{%0,%1,%2,%3}, {%4,%5,%6,%7}, {%8,%9}, {%0,%1,%2,%3};"
        : "+f"(d0), "+f"(d1), "+f"(d2), "+f"(d3)
        : "r"(a0), "r"(a1), "r"(a2), "r"(a3), "r"(b0), "r"(b1));
}

// ============================================================
// block reductions (256-thread blocks)
// ============================================================
__device__ __forceinline__ float blockReduceSum(float val) {
    __shared__ float sh[32];
    int lane = threadIdx.x & 31, wid = threadIdx.x >> 5;
    #pragma unroll
    for (int o = 16; o; o >>= 1) val += __shfl_down_sync(0xffffffffu, val, o);
    if (lane == 0) sh[wid] = val;
    __syncthreads();
    int nw = (blockDim.x + 31) >> 5;
    val = (threadIdx.x < (unsigned)nw) ? sh[threadIdx.x] : 0.f;
    if (wid == 0) {
        #pragma unroll
        for (int o = 16; o; o >>= 1) val += __shfl_down_sync(0xffffffffu, val, o);
        if (lane == 0) sh[0] = val;
    }
    __syncthreads();
    val = sh[0];
    __syncthreads();
    return val;
}
__device__ __forceinline__ float blockReduceMax(float val) {
    __shared__ float sh[32];
    int lane = threadIdx.x & 31, wid = threadIdx.x >> 5;
    #pragma unroll
    for (int o = 16; o; o >>= 1) val = fmaxf(val, __shfl_down_sync(0xffffffffu, val, o));
    if (lane == 0) sh[wid] = val;
    __syncthreads();
    int nw = (blockDim.x + 31) >> 5;
    val = (threadIdx.x < (unsigned)nw) ? sh[threadIdx.x] : -3.4e38f;
    if (wid == 0) {
        #pragma unroll
        for (int o = 16; o; o >>= 1) val = fmaxf(val, __shfl_down_sync(0xffffffffu, val, o));
        if (lane == 0) sh[0] = val;
    }
    __syncthreads();
    val = sh[0];
    __syncthreads();
    return val;
}
__device__ __forceinline__ unsigned fkey(float f) {
    unsigned u = __float_as_uint(f);
    return (u & 0x80000000u) ? ~u : (u | 0x80000000u);
}
__device__ __forceinline__ float fkeyinv(unsigned k) {
    unsigned u = (k & 0x80000000u) ? (k & 0x7FFFFFFFu) : ~k;
    return __uint_as_float(u);
}

// ============================================================
// 1) bf16 mma.sync GEMM + fused em copy:
//    g_sims[256, 16384] = inputs @ em^T, and out_em[...] = em.
//    CTA tile 128(M) x 128(N), BK=32, 8 warps (2x4), warp tile 64x32.
//    fp32 staged via cp.async (double-buffered); converted per-chunk to
//    single-buffered bf16 tiles (stride-20-uint rows: conflict-free frags).
//    B-tile write-through to out_em uses SCALAR stores (out+1 is 4B-aligned).
// ============================================================
#define BK      32
#define NCHUNK  (D_ / BK)                 // 64
#define TSTRIDE 36                        // fp32 staging: floats per row
#define TILE_F  (128 * TSTRIDE)           // 4608 floats
#define BSTRIDE 20                        // bf16 tile: uints per row (16 + 4 pad)
#define BTILE_U (128 * BSTRIDE)           // 2560 uints = 10240 B
#define GEMM_SMEM (4 * TILE_F * 4 + 2 * BTILE_U * 4)   // 73728 + 20480 = 94208 B

__global__ void __launch_bounds__(256, 2) gemm_mma_kernel(const float* __restrict__ inp,
                                                          const float* __restrict__ em,
                                                          float* __restrict__ out_em) {
    extern __shared__ float smem[];
    const int tid  = threadIdx.x;
    const int lane = tid & 31;
    const int wid  = tid >> 5;
    const int wm   = wid >> 2;            // 0..1 -> 64 M rows
    const int wn   = wid & 3;             // 0..3 -> 32 N cols
    const int bm   = blockIdx.y * 128;
    const int bmid = blockIdx.y;          // 0 or 1
    const int bn   = blockIdx.x * 128;

    const uint32_t sb = smem_u32(smem);
    uint32_t* Abf = (uint32_t*)(smem + 4 * TILE_F);
    uint32_t* Bbf = Abf + BTILE_U;

    int rowi[4], segi[4];
    #pragma unroll
    for (int i = 0; i < 4; i++) {
        int idx = i * 256 + tid;          // 0..1023
        rowi[i] = idx >> 3;               // 0..127
        segi[i] = idx & 7;                // 0..7
    }

    auto issue_chunk = [&](int k, int b) {
        const int k0 = k * BK;
        const uint32_t abase = sb + (uint32_t)(b * 2) * (TILE_F * 4);
        const uint32_t bbase = sb + (uint32_t)(b * 2 + 1) * (TILE_F * 4);
        #pragma unroll
        for (int i = 0; i < 4; i++) {
            const int row = rowi[i], seg = segi[i];
            const uint32_t soff = (uint32_t)(row * (TSTRIDE * 4) + seg * 16);
            cp_async16(abase + soff, inp + (size_t)(bm + row) * D_ + k0 + seg * 4);
            cp_async16(bbase + soff, em  + (size_t)(bn + row) * D_ + k0 + seg * 4);
        }
        CP_COMMIT();
    };

    float acc[4][4][4];
    #pragma unroll
    for (int mi = 0; mi < 4; mi++)
        #pragma unroll
        for (int ni = 0; ni < 4; ni++)
            #pragma unroll
            for (int j = 0; j < 4; j++) acc[mi][ni][j] = 0.f;

    issue_chunk(0, 0);
    issue_chunk(1, 1);
    CP_WAIT1();
    __syncthreads();

    for (int k = 0; k < NCHUNK; k++) {
        const int b = k & 1;
        float* As = smem + (b * 2)     * TILE_F;
        float* Bs = smem + (b * 2 + 1) * TILE_F;
        const int k0 = k * BK;
        const bool do_copy = ((k >> 5) == bmid);

        // fp32 staging -> bf16 tiles (+ scalar write-through em copy)
        #pragma unroll
        for (int i = 0; i < 4; i++) {
            const int row = rowi[i], seg = segi[i];
            const int so = row * TSTRIDE + seg * 4;
            float4 ra = *(float4*)(As + so);
            float4 rb = *(float4*)(Bs + so);
            if (do_copy) {
                float* d = out_em + (size_t)(bn + row) * D_ + k0 + seg * 4;
                d[0] = rb.x; d[1] = rb.y; d[2] = rb.z; d[3] = rb.w;   // 4B-aligned base: scalar only
            }
            const int bo = row * BSTRIDE + seg * 2;
            Abf[bo]     = pk_bf16(ra.x, ra.y);
            Abf[bo + 1] = pk_bf16(ra.z, ra.w);
            Bbf[bo]     = pk_bf16(rb.x, rb.y);
            Bbf[bo + 1] = pk_bf16(rb.z, rb.w);
        }
        __syncthreads();

        #pragma unroll
        for (int kk = 0; kk < 2; kk++) {                // two k16 steps per BK=32
            const int cu = kk * 8 + (lane & 3);         // uint col within row
            uint32_t af[4][4], bf[4][2];
            #pragma unroll
            for (int mi = 0; mi < 4; mi++) {
                const int r = wm * 64 + mi * 16 + (lane >> 2);
                af[mi][0] = Abf[r * BSTRIDE + cu];
                af[mi][1] = Abf[(r + 8) * BSTRIDE + cu];
                af[mi][2] = Abf[r * BSTRIDE + cu + 4];
                af[mi][3] = Abf[(r + 8) * BSTRIDE + cu + 4];
            }
            #pragma unroll
            for (int ni = 0; ni < 4; ni++) {
                const int n = wn * 32 + ni * 8 + (lane >> 2);
                bf[ni][0] = Bbf[n * BSTRIDE + cu];
                bf[ni][1] = Bbf[n * BSTRIDE + cu + 4];
            }
            #pragma unroll
            for (int mi = 0; mi < 4; mi++)
                #pragma unroll
                for (int ni = 0; ni < 4; ni++)
                    mma_bf16(acc[mi][ni][0], acc[mi][ni][1], acc[mi][ni][2], acc[mi][ni][3],
                             af[mi][0], af[mi][1], af[mi][2], af[mi][3],
                             bf[ni][0], bf[ni][1]);
        }

        __syncthreads();
        if (k + 2 < NCHUNK) issue_chunk(k + 2, b);
        else CP_COMMIT();                 // keep group count uniform
        CP_WAIT1();
        __syncthreads();
    }

    // epilogue (g_sims is 16B-aligned: float2 OK)
    #pragma unroll
    for (int mi = 0; mi < 4; mi++) {
        const int r0 = bm + wm * 64 + mi * 16 + (lane >> 2);
        #pragma unroll
        for (int ni = 0; ni < 4; ni++) {
            const int c = bn + wn * 32 + ni * 8 + (lane & 3) * 2;
            *(float2*)(g_sims + (size_t)r0 * CM_ + c)       = make_float2(acc[mi][ni][0], acc[mi][ni][1]);
            *(float2*)(g_sims + (size_t)(r0 + 8) * CM_ + c) = make_float2(acc[mi][ni][2], acc[mi][ni][3]);
        }
    }
}

// ============================================================
// 2) per-sample loss: CE + hard-negative term.
//    Top-50 via statistical threshold (mu + z*sigma) + compaction,
//    exact selection on candidates; full binary-search fallback.
// ============================================================
#define CAP   768
#define LOSS_SMEM (CM_ * 4 + CAP * 4)

__global__ void __launch_bounds__(256) loss_kernel(const int* __restrict__ targets,
                                                   const int* __restrict__ cams,
                                                   const int* __restrict__ ep) {
    extern __shared__ float srow[];                       // CM_ floats
    unsigned* buf = (unsigned*)(srow + CM_);              // CAP keys
    __shared__ float spos[C_];
    __shared__ unsigned s_cnt;

    const int b = blockIdx.x, tid = threadIdx.x;
    const int target = targets[b], cam = cams[b];
    const float* row = g_sims + (size_t)b * CM_;

    if (tid == 0) s_cnt = 0;

    // stage row (mask positives) + accumulate max/sum/sumsq
    float lmax = -3.4e38f, lsum = 0.f, lsq = 0.f;
    for (int i = tid; i < CM_; i += 256) {
        float v = row[i];
        if ((i & (M_ - 1)) == target) v = -1000.f;
        srow[i] = v;
        lmax = fmaxf(lmax, v);
        lsum += v;
        lsq  += v * v;
    }
    if (tid < C_) spos[tid] = row[tid * M_ + target];
    __syncthreads();

    const float gm  = blockReduceMax(lmax);
    float sum = blockReduceSum(lsum) + 8000.f;            // remove 8 masked -1000s
    float sq  = blockReduceSum(lsq) - 8.e6f;
    const float nvalid = (float)(CM_ - C_);
    const float mu  = sum / nvalid;
    const float sig = sqrtf(fmaxf(sq / nvalid - mu * mu, 1e-20f));

    float cnt = blockReduceSum((cams[tid] == cam) ? 1.f : 0.f);

    // ---- intra-camera CE ----
    float mx = -3.4e38f;
    for (int i = cam * M_ + tid; i < (cam + 1) * M_; i += 256) mx = fmaxf(mx, srow[i]);
    mx = fmaxf(mx, spos[cam]);
    mx = blockReduceMax(mx);
    float s = 0.f;
    for (int i = cam * M_ + tid; i < (cam + 1) * M_; i += 256)
        s += __expf((srow[i] - mx) * INVT);
    s = blockReduceSum(s);
    s += __expf((spos[cam] - mx) * INVT);
    float ce = mx * INVT + __logf(s) - spos[cam] * INVT;

    // ---- hard-negative associate loss ----
    int epoch = ep ? ep[0] : 6;
    float al = 0.f;
    if (epoch >= 5) {
        float pm = -3.4e38f, psum = 0.f;
        #pragma unroll
        for (int c2 = 0; c2 < C_; c2++) { pm = fmaxf(pm, spos[c2]); psum += spos[c2]; }
        const float mm = fmaxf(gm, pm) * INVT;

        // adaptive threshold: expect ~134 candidates at z=2.4
        float z = 2.4f, t = mu + z * sig;
        bool ok = false;
        for (int it = 0; it < 8; it++) {
            float c = 0.f;
            for (int i = tid; i < CM_; i += 256) c += (srow[i] >= t) ? 1.f : 0.f;
            c = blockReduceSum(c);
            if (c >= (float)KNN && c <= (float)CAP) { ok = true; break; }
            if (c < (float)KNN) z -= 0.5f; else z += 0.45f;
            t = mu + z * sig;
        }

        unsigned k50;
        float cg, sn;
        if (ok) {
            for (int i = tid; i < CM_; i += 256) {
                float v = srow[i];
                if (v >= t) { unsigned p = atomicAdd(&s_cnt, 1u); buf[p] = fkey(v); }
            }
            __syncthreads();
            const int S = (int)s_cnt;
            unsigned lo = fkey(t), hi = fkey(gm);
            while (lo < hi) {
                unsigned mid = (unsigned)((((unsigned long long)lo) + hi + 1ull) >> 1);
                float c = 0.f;
                for (int i = tid; i < S; i += 256) c += (buf[i] >= mid) ? 1.f : 0.f;
                c = blockReduceSum(c);
                if (c >= (float)KNN) lo = mid; else hi = mid - 1u;
            }
            k50 = lo;
            float cgl = 0.f, snl = 0.f;
            for (int i = tid; i < S; i += 256) {
                unsigned k = buf[i];
                if (k > k50) { cgl += 1.f; snl += __expf(fkeyinv(k) * INVT - mm); }
            }
            cg = blockReduceSum(cgl);
            sn = blockReduceSum(snl);
        } else {
            // exact fallback: full-key binary search over the whole row
            unsigned lo = 0u, hi = fkey(gm);
            while (lo < hi) {
                unsigned mid = (unsigned)((((unsigned long long)lo) + hi + 1ull) >> 1);
                float c = 0.f;
                for (int i = tid; i < CM_; i += 256)
                    c += (fkey(srow[i]) >= mid) ? 1.f : 0.f;
                c = blockReduceSum(c);
                if (c >= (float)KNN) lo = mid; else hi = mid - 1u;
            }
            k50 = lo;
            float cgl = 0.f, snl = 0.f;
            for (int i = tid; i < CM_; i += 256) {
                float v = srow[i];
                if (fkey(v) > k50) { cgl += 1.f; snl += __expf(v * INVT - mm); }
            }
            cg = blockReduceSum(cgl);
            sn = blockReduceSum(snl);
        }

        const float v50 = fkeyinv(k50);
        sn += ((float)KNN - cg) * __expf(v50 * INVT - mm);   // tie-correct

        float sp = 0.f;
        #pragma unroll
        for (int c2 = 0; c2 < C_; c2++) sp += __expf(spos[c2] * INVT - mm);
        float lse = mm + __logf(sp + sn);
        al = lse - psum * INVT / (float)C_;
    }

    if (tid == 0) g_partial[b] = (ce + 0.5f * al) / cnt;
}

// ============================================================
// 3) EMA scatter + renorm, with fused final loss reduction (block 0)
// ============================================================
__global__ void __launch_bounds__(256) ema_kernel(const float* __restrict__ inp,
                                                  const int* __restrict__ targets,
                                                  const int* __restrict__ cams,
                                                  float* __restrict__ out) {
    __shared__ int srid[B_];
    const int b = blockIdx.x, tid = threadIdx.x;
    float* em_out = out + 1;

    if (b == 0) {                       // fused finish: sum g_partial -> out[0]
        float v = g_partial[tid];
        v = blockReduceSum(v);
        if (tid == 0) out[0] = v;
    }

    srid[tid] = cams[tid] * M_ + targets[tid];
    __syncthreads();
    const int r = srid[b];
    for (int bp = 0; bp < b; bp++)
        if (srid[bp] == r) return;   // not the owner

    float v[8];
    const size_t base = (size_t)r * D_ + tid * 8;
    #pragma unroll
    for (int j = 0; j < 8; j++) v[j] = em_out[base + j];

    for (int bb = b; bb < B_; bb++) {
        if (srid[bb] != r) continue;
        const float4* ip = (const float4*)(inp + (size_t)bb * D_ + tid * 8);
        float4 i0 = ip[0], i1 = ip[1];
        float xv[8] = {i0.x, i0.y, i0.z, i0.w, i1.x, i1.y, i1.z, i1.w};
        float ss = 0.f;
        #pragma unroll
        for (int j = 0; j < 8; j++) {
            v[j] = 0.2f * v[j] + 0.8f * xv[j];
            ss += v[j] * v[j];
        }
        ss = blockReduceSum(ss);
        float inv = rsqrtf(ss);
        #pragma unroll
        for (int j = 0; j < 8; j++) v[j] *= inv;
    }
    #pragma unroll
    for (int j = 0; j < 8; j++) em_out[base + j] = v[j];
}

// ============================================================
extern "C" void kernel_launch(void* const* d_in, const int* in_sizes, int n_in,
                              void* d_out, int out_size) {
    const float* inp     = (const float*)d_in[0];
    const float* em      = (const float*)d_in[1];
    const int*   targets = (const int*)d_in[2];
    const int*   cams    = (const int*)d_in[3];
    const int*   ep      = (n_in >= 5) ? (const int*)d_in[4] : nullptr;
    float* out = (float*)d_out;

    cudaFuncSetAttribute(loss_kernel, cudaFuncAttributeMaxDynamicSharedMemorySize, LOSS_SMEM);
    cudaFuncSetAttribute(gemm_mma_kernel, cudaFuncAttributeMaxDynamicSharedMemorySize, GEMM_SMEM);

    dim3 gg(CM_ / 128, B_ / 128);
    gemm_mma_kernel<<<gg, 256, GEMM_SMEM>>>(inp, em, out + 1);
    loss_kernel<<<B_, 256, LOSS_SMEM>>>(targets, cams, ep);
    ema_kernel<<<B_, 256>>>(inp, targets, cams, out);
}

// round 11
// speedup vs baseline: 6.0223x; 1.2424x over previous
#include <cuda_runtime.h>
#include <cstdint>

#define C_   8
#define M_   2048
#define D_   2048
#define B_   256
#define CM_  (C_ * M_)
#define KNN  50
#define INVT 20.0f   // 1/TEMP

// ---- scratch (device globals: allocation-free rule) ----
__device__ float g_sims[(size_t)B_ * CM_];   // 16 MB

// ============================================================
// helpers
// ============================================================
__device__ __forceinline__ uint32_t smem_u32(const void* p) {
    uint32_t a;
    asm("{ .reg .u64 t; cvta.to.shared.u64 t, %1; cvt.u32.u64 %0, t; }" : "=r"(a) : "l"(p));
    return a;
}
__device__ __forceinline__ uint32_t pk_bf16(float lo, float hi) {
    uint32_t r;
    asm("cvt.rn.bf16x2.f32 %0, %1, %2;" : "=r"(r) : "f"(hi), "f"(lo));   // d.hi=%1, d.lo=%2
    return r;
}
__device__ __forceinline__ void ldsm_x4(uint32_t& r0, uint32_t& r1, uint32_t& r2, uint32_t& r3,
                                        uint32_t addr) {
    asm volatile("ldmatrix.sync.aligned.m8n8.x4.shared.b16 {%0,%1,%2,%3}, [%4];"
                 : "=r"(r0), "=r"(r1), "=r"(r2), "=r"(r3) : "r"(addr));
}
__device__ __forceinline__ void mma_bf16(float& d0, float& d1, float& d2, float& d3,
                                         uint32_t a0, uint32_t a1, uint32_t a2, uint32_t a3,
                                         uint32_t b0, uint32_t b1) {
    asm volatile(
        "mma.sync.aligned.m16n8k16.row.col.f32.bf16.bf16.f32 "
        "{%0,%1,%2,%3}, {%4,%5,%6,%7}, {%8,%9}, {%0,%1,%2,%3};"
        : "+f"(d0), "+f"(d1), "+f"(d2), "+f"(d3)
        : "r"(a0), "r"(a1), "r"(a2), "r"(a3), "r"(b0), "r"(b1));
}

// ============================================================
// block reductions (256-thread blocks)
// ============================================================
__device__ __forceinline__ float blockReduceSum(float val) {
    __shared__ float sh[32];
    int lane = threadIdx.x & 31, wid = threadIdx.x >> 5;
    #pragma unroll
    for (int o = 16; o; o >>= 1) val += __shfl_down_sync(0xffffffffu, val, o);
    if (lane == 0) sh[wid] = val;
    __syncthreads();
    int nw = (blockDim.x + 31) >> 5;
    val = (threadIdx.x < (unsigned)nw) ? sh[threadIdx.x] : 0.f;
    if (wid == 0) {
        #pragma unroll
        for (int o = 16; o; o >>= 1) val += __shfl_down_sync(0xffffffffu, val, o);
        if (lane == 0) sh[0] = val;
    }
    __syncthreads();
    val = sh[0];
    __syncthreads();
    return val;
}
__device__ __forceinline__ float blockReduceMax(float val) {
    __shared__ float sh[32];
    int lane = threadIdx.x & 31, wid = threadIdx.x >> 5;
    #pragma unroll
    for (int o = 16; o; o >>= 1) val = fmaxf(val, __shfl_down_sync(0xffffffffu, val, o));
    if (lane == 0) sh[wid] = val;
    __syncthreads();
    int nw = (blockDim.x + 31) >> 5;
    val = (threadIdx.x < (unsigned)nw) ? sh[threadIdx.x] : -3.4e38f;
    if (wid == 0) {
        #pragma unroll
        for (int o = 16; o; o >>= 1) val = fmaxf(val, __shfl_down_sync(0xffffffffu, val, o));
        if (lane == 0) sh[0] = val;
    }
    __syncthreads();
    val = sh[0];
    __syncthreads();
    return val;
}
__device__ __forceinline__ unsigned fkey(float f) {
    unsigned u = __float_as_uint(f);
    return (u & 0x80000000u) ? ~u : (u | 0x80000000u);
}
__device__ __forceinline__ float fkeyinv(unsigned k) {
    unsigned u = (k & 0x80000000u) ? (k & 0x7FFFFFFFu) : ~k;
    return __uint_as_float(u);
}

// ============================================================
// 1) bf16 mma.sync GEMM + fused em copy (no fp32 staging):
//    LDG fp32 -> reg-convert -> bf16 smem tiles (double buffered),
//    ldmatrix fragments, one __syncthreads per K chunk.
//    CTA 128x128, 8 warps (2x4), warp tile 64x32, BK=32.
//    Also zeroes out[0] (loss accumulator) each launch.
// ============================================================
#define BK      32
#define NCHUNK  (D_ / BK)                 // 64
#define BSTRIDE 20                        // uints per bf16 tile row (16 + 4 pad)
#define BTILE_U (128 * BSTRIDE)           // 2560 uints = 10240 B
#define GEMM_SMEM (4 * BTILE_U * 4)       // 40960 B

__global__ void __launch_bounds__(256, 2) gemm_mma_kernel(const float* __restrict__ inp,
                                                          const float* __restrict__ em,
                                                          float* __restrict__ out) {
    extern __shared__ uint32_t smem[];    // [buf0:A,B][buf1:A,B]
    const int tid  = threadIdx.x;
    const int lane = tid & 31;
    const int wid  = tid >> 5;
    const int wm   = wid >> 2;            // 0..1 -> 64 M rows
    const int wn   = wid & 3;             // 0..3 -> 32 N cols
    const int bm   = blockIdx.y * 128;
    const int bmid = blockIdx.y;          // 0 or 1
    const int bn   = blockIdx.x * 128;

    float* out_em = out + 1;
    if (blockIdx.x == 0 && blockIdx.y == 0 && tid == 0) out[0] = 0.f;

    const uint32_t sb = smem_u32(smem);

    // per-thread load/STS mapping: thread handles rows r0 + i*32, segment s
    const int r0 = tid >> 3;              // 0..31
    const int s  = tid & 7;               // 0..7 (float4 segment)
    const float* gA0 = inp + (size_t)(bm + r0) * D_ + s * 4;
    const float* gB0 = em  + (size_t)(bn + r0) * D_ + s * 4;
    float*       oe0 = out_em + (size_t)(bn + r0) * D_ + s * 4;
    const int soff0 = r0 * BSTRIDE + s * 2;          // uint index in tile

    // per-lane ldmatrix offsets (byte)
    const int lrow  = (lane & 7) + ((lane >> 3) & 1) * 8;   // 0..15
    const int lcolu = ((lane >> 4) & 1) * 4;                // 0 or 4 uints
    const uint32_t aoff = (uint32_t)(((wm * 64 + lrow) * BSTRIDE + lcolu) * 4);
    const uint32_t boff = (uint32_t)(((wn * 32 + lrow) * BSTRIDE + lcolu) * 4);

    float acc[4][4][4];
    #pragma unroll
    for (int mi = 0; mi < 4; mi++)
        #pragma unroll
        for (int ni = 0; ni < 4; ni++)
            #pragma unroll
            for (int j = 0; j < 4; j++) acc[mi][ni][j] = 0.f;

    float4 curA[4], curB[4];
    #pragma unroll
    for (int i = 0; i < 4; i++) {
        curA[i] = __ldg((const float4*)(gA0 + (size_t)i * 32 * D_));
        curB[i] = __ldg((const float4*)(gB0 + (size_t)i * 32 * D_));
    }

    for (int k = 0; k < NCHUNK; k++) {
        const int buf = k & 1;
        uint32_t* Ab = smem + buf * 2 * BTILE_U;
        uint32_t* Bb = Ab + BTILE_U;
        const bool do_copy = ((k >> 5) == bmid);
        const int k0 = k * BK;

        // convert chunk k to bf16 tiles (+ scalar write-through em copy)
        #pragma unroll
        for (int i = 0; i < 4; i++) {
            const int so = soff0 + i * (32 * BSTRIDE);
            if (do_copy) {
                float* d = oe0 + (size_t)i * 32 * D_ + k0;
                d[0] = curB[i].x; d[1] = curB[i].y; d[2] = curB[i].z; d[3] = curB[i].w;
            }
            Ab[so]     = pk_bf16(curA[i].x, curA[i].y);
            Ab[so + 1] = pk_bf16(curA[i].z, curA[i].w);
            Bb[so]     = pk_bf16(curB[i].x, curB[i].y);
            Bb[so + 1] = pk_bf16(curB[i].z, curB[i].w);
        }
        __syncthreads();

        // prefetch chunk k+1 into regs
        if (k + 1 < NCHUNK) {
            const float* pa = gA0 + (k + 1) * BK;
            const float* pb = gB0 + (k + 1) * BK;
            #pragma unroll
            for (int i = 0; i < 4; i++) {
                curA[i] = __ldg((const float4*)(pa + (size_t)i * 32 * D_));
                curB[i] = __ldg((const float4*)(pb + (size_t)i * 32 * D_));
            }
        }

        // fragments via ldmatrix + MMA
        const uint32_t Abase = sb + (uint32_t)(buf * 2 * BTILE_U * 4) + aoff;
        const uint32_t Bbase = sb + (uint32_t)(buf * 2 * BTILE_U * 4) + (uint32_t)(BTILE_U * 4) + boff;
        #pragma unroll
        for (int kk = 0; kk < 2; kk++) {
            uint32_t b0, b1, b2, b3, b4, b5, b6, b7;
            ldsm_x4(b0, b1, b2, b3, Bbase + kk * 32);            // n 0-15 of warp tile
            ldsm_x4(b4, b5, b6, b7, Bbase + 1280 + kk * 32);     // n 16-31
            #pragma unroll
            for (int mi = 0; mi < 4; mi++) {
                uint32_t a0, a1, a2, a3;
                ldsm_x4(a0, a1, a2, a3, Abase + mi * 1280 + kk * 32);
                mma_bf16(acc[mi][0][0], acc[mi][0][1], acc[mi][0][2], acc[mi][0][3],
                         a0, a1, a2, a3, b0, b2);
                mma_bf16(acc[mi][1][0], acc[mi][1][1], acc[mi][1][2], acc[mi][1][3],
                         a0, a1, a2, a3, b1, b3);
                mma_bf16(acc[mi][2][0], acc[mi][2][1], acc[mi][2][2], acc[mi][2][3],
                         a0, a1, a2, a3, b4, b6);
                mma_bf16(acc[mi][3][0], acc[mi][3][1], acc[mi][3][2], acc[mi][3][3],
                         a0, a1, a2, a3, b5, b7);
            }
        }
        // no trailing sync needed: next STS targets the other buffer, and
        // all warps passed this chunk's sync before any next-chunk STS.
    }

    // epilogue (g_sims 16B-aligned: float2 OK)
    #pragma unroll
    for (int mi = 0; mi < 4; mi++) {
        const int rr = bm + wm * 64 + mi * 16 + (lane >> 2);
        #pragma unroll
        for (int ni = 0; ni < 4; ni++) {
            const int c = bn + wn * 32 + ni * 8 + (lane & 3) * 2;
            *(float2*)(g_sims + (size_t)rr * CM_ + c)       = make_float2(acc[mi][ni][0], acc[mi][ni][1]);
            *(float2*)(g_sims + (size_t)(rr + 8) * CM_ + c) = make_float2(acc[mi][ni][2], acc[mi][ni][3]);
        }
    }
}

// ============================================================
// 2) fused loss + EMA + final reduction.
//    Loss: CE + hard-negative (statistical threshold top-50, exact).
//    Each block b atomically adds its contribution to out[0]
//    (out[0] zeroed by gemm kernel each replay).
//    EMA: block b owns row chain if b is first occurrence.
// ============================================================
#define CAP   768
#define LOSS_SMEM (CM_ * 4 + CAP * 4)

__global__ void __launch_bounds__(256) loss_ema_kernel(const float* __restrict__ inp,
                                                       const int* __restrict__ targets,
                                                       const int* __restrict__ cams,
                                                       const int* __restrict__ ep,
                                                       float* __restrict__ out) {
    extern __shared__ float srow[];                       // CM_ floats
    unsigned* buf = (unsigned*)(srow + CM_);              // CAP keys
    __shared__ float spos[C_];
    __shared__ unsigned s_cnt;
    __shared__ int srid[B_];

    const int b = blockIdx.x, tid = threadIdx.x;
    const int target = targets[b], cam = cams[b];
    const float* row = g_sims + (size_t)b * CM_;
    float* em_out = out + 1;

    if (tid == 0) s_cnt = 0;
    srid[tid] = cams[tid] * M_ + targets[tid];

    // stage row (mask positives) + accumulate max/sum/sumsq
    float lmax = -3.4e38f, lsum = 0.f, lsq = 0.f;
    for (int i = tid; i < CM_; i += 256) {
        float v = row[i];
        if ((i & (M_ - 1)) == target) v = -1000.f;
        srow[i] = v;
        lmax = fmaxf(lmax, v);
        lsum += v;
        lsq  += v * v;
    }
    if (tid < C_) spos[tid] = row[tid * M_ + target];
    __syncthreads();

    const float gm  = blockReduceMax(lmax);
    float sum = blockReduceSum(lsum) + 8000.f;            // remove 8 masked -1000s
    float sq  = blockReduceSum(lsq) - 8.e6f;
    const float nvalid = (float)(CM_ - C_);
    const float mu  = sum / nvalid;
    const float sig = sqrtf(fmaxf(sq / nvalid - mu * mu, 1e-20f));

    float cnt = blockReduceSum((cams[tid] == cam) ? 1.f : 0.f);

    // ---- intra-camera CE ----
    float mx = -3.4e38f;
    for (int i = cam * M_ + tid; i < (cam + 1) * M_; i += 256) mx = fmaxf(mx, srow[i]);
    mx = fmaxf(mx, spos[cam]);
    mx = blockReduceMax(mx);
    float s = 0.f;
    for (int i = cam * M_ + tid; i < (cam + 1) * M_; i += 256)
        s += __expf((srow[i] - mx) * INVT);
    s = blockReduceSum(s);
    s += __expf((spos[cam] - mx) * INVT);
    float ce = mx * INVT + __logf(s) - spos[cam] * INVT;

    // ---- hard-negative associate loss ----
    int epoch = ep ? ep[0] : 6;
    float al = 0.f;
    if (epoch >= 5) {
        float pm = -3.4e38f, psum = 0.f;
        #pragma unroll
        for (int c2 = 0; c2 < C_; c2++) { pm = fmaxf(pm, spos[c2]); psum += spos[c2]; }
        const float mm = fmaxf(gm, pm) * INVT;

        // adaptive threshold: expect ~134 candidates at z=2.4
        float z = 2.4f, t = mu + z * sig;
        bool ok = false;
        for (int it = 0; it < 8; it++) {
            float c = 0.f;
            for (int i = tid; i < CM_; i += 256) c += (srow[i] >= t) ? 1.f : 0.f;
            c = blockReduceSum(c);
            if (c >= (float)KNN && c <= (float)CAP) { ok = true; break; }
            if (c < (float)KNN) z -= 0.5f; else z += 0.45f;
            t = mu + z * sig;
        }

        unsigned k50;
        float cg, sn;
        if (ok) {
            for (int i = tid; i < CM_; i += 256) {
                float v = srow[i];
                if (v >= t) { unsigned p = atomicAdd(&s_cnt, 1u); buf[p] = fkey(v); }
            }
            __syncthreads();
            const int S = (int)s_cnt;
            unsigned lo = fkey(t), hi = fkey(gm);
            while (lo < hi) {
                unsigned mid = (unsigned)((((unsigned long long)lo) + hi + 1ull) >> 1);
                float c = 0.f;
                for (int i = tid; i < S; i += 256) c += (buf[i] >= mid) ? 1.f : 0.f;
                c = blockReduceSum(c);
                if (c >= (float)KNN) lo = mid; else hi = mid - 1u;
            }
            k50 = lo;
            float cgl = 0.f, snl = 0.f;
            for (int i = tid; i < S; i += 256) {
                unsigned kk = buf[i];
                if (kk > k50) { cgl += 1.f; snl += __expf(fkeyinv(kk) * INVT - mm); }
            }
            cg = blockReduceSum(cgl);
            sn = blockReduceSum(snl);
        } else {
            // exact fallback: full-key binary search over the whole row
            unsigned lo = 0u, hi = fkey(gm);
            while (lo < hi) {
                unsigned mid = (unsigned)((((unsigned long long)lo) + hi + 1ull) >> 1);
                float c = 0.f;
                for (int i = tid; i < CM_; i += 256)
                    c += (fkey(srow[i]) >= mid) ? 1.f : 0.f;
                c = blockReduceSum(c);
                if (c >= (float)KNN) lo = mid; else hi = mid - 1u;
            }
            k50 = lo;
            float cgl = 0.f, snl = 0.f;
            for (int i = tid; i < CM_; i += 256) {
                float v = srow[i];
                if (fkey(v) > k50) { cgl += 1.f; snl += __expf(v * INVT - mm); }
            }
            cg = blockReduceSum(cgl);
            sn = blockReduceSum(snl);
        }

        const float v50 = fkeyinv(k50);
        sn += ((float)KNN - cg) * __expf(v50 * INVT - mm);   // tie-correct

        float sp = 0.f;
        #pragma unroll
        for (int c2 = 0; c2 < C_; c2++) sp += __expf(spos[c2] * INVT - mm);
        float lse = mm + __logf(sp + sn);
        al = lse - psum * INVT / (float)C_;
    }

    if (tid == 0) atomicAdd(out, (ce + 0.5f * al) / cnt);

    // ---- fused EMA scatter + renorm (block-uniform ownership) ----
    __syncthreads();                       // srid complete (also done long ago)
    const int r = srid[b];
    bool owner = true;
    for (int bp = 0; bp < b; bp++)
        if (srid[bp] == r) { owner = false; break; }
    if (!owner) return;

    float v[8];
    const size_t base = (size_t)r * D_ + tid * 8;
    #pragma unroll
    for (int j = 0; j < 8; j++) v[j] = em_out[base + j];

    for (int bb = b; bb < B_; bb++) {
        if (srid[bb] != r) continue;       // uniform across block
        const float4* ip = (const float4*)(inp + (size_t)bb * D_ + tid * 8);
        float4 i0 = ip[0], i1 = ip[1];
        float xv[8] = {i0.x, i0.y, i0.z, i0.w, i1.x, i1.y, i1.z, i1.w};
        float ss = 0.f;
        #pragma unroll
        for (int j = 0; j < 8; j++) {
            v[j] = 0.2f * v[j] + 0.8f * xv[j];
            ss += v[j] * v[j];
        }
        ss = blockReduceSum(ss);
        float inv = rsqrtf(ss);
        #pragma unroll
        for (int j = 0; j < 8; j++) v[j] *= inv;
    }
    #pragma unroll
    for (int j = 0; j < 8; j++) em_out[base + j] = v[j];
}

// ============================================================
extern "C" void kernel_launch(void* const* d_in, const int* in_sizes, int n_in,
                              void* d_out, int out_size) {
    const float* inp     = (const float*)d_in[0];
    const float* em      = (const float*)d_in[1];
    const int*   targets = (const int*)d_in[2];
    const int*   cams    = (const int*)d_in[3];
    const int*   ep      = (n_in >= 5) ? (const int*)d_in[4] : nullptr;
    float* out = (float*)d_out;

    cudaFuncSetAttribute(loss_ema_kernel, cudaFuncAttributeMaxDynamicSharedMemorySize, LOSS_SMEM);
    cudaFuncSetAttribute(gemm_mma_kernel, cudaFuncAttributeMaxDynamicSharedMemorySize, GEMM_SMEM);

    dim3 gg(CM_ / 128, B_ / 128);
    gemm_mma_kernel<<<gg, 256, GEMM_SMEM>>>(inp, em, out);
    loss_ema_kernel<<<B_, 256, LOSS_SMEM>>>(inp, targets, cams, ep, out);
}